// round 1
// baseline (speedup 1.0000x reference)
#include <cuda_runtime.h>
#include <math.h>

#define BATCH    4096
#define HLEN_MAX 200
#define DIM      64
#define NTHREADS 256

// smem layout in floats:
//  hist : [0, 12800)        (200 x 64)
//  hid  : [12800, 13000)    (int, 200)
//  tgt  : [13000, 13064)
//  sc   : [13064, 13264)    scores -> softmax weights
//  red  : [13264, 13520)    reduction scratch (256)
//  comb : [13520, 13712)    (192)
//  z1   : [13712, 13840)    (128)
//  z2   : [13840, 13904)    (64)
#define SMEM_FLOATS 13904
#define SMEM_BYTES  (SMEM_FLOATS * 4)

__global__ __launch_bounds__(NTHREADS, 2)
void din_kernel(const int*   __restrict__ item_ids,
                const int*   __restrict__ history,
                const int*   __restrict__ hist_len,
                const float* __restrict__ emb,
                const float* __restrict__ aW1,
                const float* __restrict__ ab1,
                const float* __restrict__ aW2,
                const float* __restrict__ fW1,
                const float* __restrict__ fb1,
                const float* __restrict__ fW2,
                const float* __restrict__ fb2,
                const float* __restrict__ fW3,
                const float* __restrict__ fb3,
                float*       __restrict__ out)
{
    extern __shared__ float sm[];
    float* hist_s = sm;
    int*   hid_s  = (int*)(sm + 12800);
    float* tgt_s  = sm + 13000;
    float* sc_s   = sm + 13064;
    float* red_s  = sm + 13264;
    float* comb_s = sm + 13520;
    float* z1_s   = sm + 13712;
    float* z2_s   = sm + 13840;

    const int b    = blockIdx.x;
    const int tid  = threadIdx.x;
    const int j    = tid & 63;   // output column of attention FC
    const int g    = tid >> 6;   // row group (0..3)
    const int lane = tid & 31;
    const int wid  = tid >> 5;

    // ---- stage 1: history ids, target embedding, zero the score accumulators
    if (tid < HLEN_MAX) {
        hid_s[tid] = history[b * HLEN_MAX + tid];
        sc_s[tid]  = 0.f;
    }
    if (tid < 16) {
        int iid = item_ids[b];
        ((float4*)tgt_s)[tid] = ((const float4*)(emb + (size_t)iid * DIM))[tid];
    }
    __syncthreads();

    const int hlen = hist_len[b];

    // ---- stage 2: gather history embeddings -> smem (masked with zeros past hlen)
    for (int idx = tid; idx < HLEN_MAX * 16; idx += NTHREADS) {
        int row = idx >> 4;
        int c   = idx & 15;
        float4 v = make_float4(0.f, 0.f, 0.f, 0.f);
        if (row < hlen) {
            int h = hid_s[row];
            v = ((const float4*)(emb + (size_t)h * DIM))[c];
        }
        ((float4*)hist_s)[idx] = v;
        (void)c;
    }

    // ---- stage 3: per-batch fused matrix column:
    //      mcol[d] = A1[d][j] + tgt[d]*A3[d][j]
    //      cj      = ab1[j] + sum_d tgt[d]*A2[d][j]
    // aW1 is [3D, D] row-major: rows [0,64)=A1, [64,128)=A2, [128,192)=A3
    float mcol[DIM];
    float cj = __ldg(ab1 + j);
    #pragma unroll
    for (int d = 0; d < DIM; d++) {
        float t = tgt_s[d];
        mcol[d] = fmaf(t, __ldg(aW1 + (128 + d) * DIM + j), __ldg(aW1 + d * DIM + j));
        cj      = fmaf(t, __ldg(aW1 + (64 + d) * DIM + j), cj);
    }
    const float w2j = __ldg(aW2 + j);   // aW2 is [D,1]
    __syncthreads();

    // ---- stage 4: scores[l] = relu(hist_l @ mcol + cj) . aW2   (ab2 dropped: softmax-invariant)
    // thread (j, g) handles rows l0 = 8*li + g and l1 = l0 + 4  (li = 0..24)
    for (int li = 0; li < 25; li++) {
        int l0 = li * 8 + g;
        int l1 = l0 + 4;
        const float4* h0 = (const float4*)(hist_s + l0 * DIM);
        const float4* h1 = (const float4*)(hist_s + l1 * DIM);
        float a0 = cj, a1 = cj;
        #pragma unroll
        for (int d4 = 0; d4 < 16; d4++) {
            float4 x0 = h0[d4];
            float4 x1 = h1[d4];
            a0 = fmaf(x0.x, mcol[4*d4+0], a0);
            a0 = fmaf(x0.y, mcol[4*d4+1], a0);
            a0 = fmaf(x0.z, mcol[4*d4+2], a0);
            a0 = fmaf(x0.w, mcol[4*d4+3], a0);
            a1 = fmaf(x1.x, mcol[4*d4+0], a1);
            a1 = fmaf(x1.y, mcol[4*d4+1], a1);
            a1 = fmaf(x1.z, mcol[4*d4+2], a1);
            a1 = fmaf(x1.w, mcol[4*d4+3], a1);
        }
        float s0 = fmaxf(a0, 0.f) * w2j;
        float s1 = fmaxf(a1, 0.f) * w2j;
        #pragma unroll
        for (int o = 16; o; o >>= 1) {
            s0 += __shfl_xor_sync(0xffffffffu, s0, o);
            s1 += __shfl_xor_sync(0xffffffffu, s1, o);
        }
        if (lane == 0) {
            atomicAdd(&sc_s[l0], s0);
            atomicAdd(&sc_s[l1], s1);
        }
    }
    __syncthreads();

    // ---- stage 5: softmax over sc_s[0..199]
    float v = (tid < HLEN_MAX) ? sc_s[tid] : -INFINITY;
    float m = v;
    #pragma unroll
    for (int o = 16; o; o >>= 1) m = fmaxf(m, __shfl_xor_sync(0xffffffffu, m, o));
    if (lane == 0) red_s[wid] = m;
    __syncthreads();
    float mm = red_s[0];
    #pragma unroll
    for (int w = 1; w < 8; w++) mm = fmaxf(mm, red_s[w]);

    float e = (tid < HLEN_MAX) ? __expf(v - mm) : 0.f;
    float ssum = e;
    #pragma unroll
    for (int o = 16; o; o >>= 1) ssum += __shfl_xor_sync(0xffffffffu, ssum, o);
    if (lane == 0) red_s[8 + wid] = ssum;
    __syncthreads();
    float tot = red_s[8];
    #pragma unroll
    for (int w = 1; w < 8; w++) tot += red_s[8 + w];
    float inv = 1.f / tot;
    if (tid < HLEN_MAX) sc_s[tid] = e * inv;
    __syncthreads();

    // ---- stage 6: pooled[j] = sum_l w[l] * hist[l][j]
    float p = 0.f;
    #pragma unroll 5
    for (int li = 0; li < 50; li++) {
        int l = li * 4 + g;
        p = fmaf(sc_s[l], hist_s[l * DIM + j], p);
    }
    red_s[tid] = p;
    __syncthreads();
    if (tid < DIM) {
        float pooled = red_s[tid] + red_s[64 + tid] + red_s[128 + tid] + red_s[192 + tid];
        float tg = tgt_s[tid];
        comb_s[tid]       = tg;
        comb_s[64 + tid]  = pooled;
        comb_s[128 + tid] = pooled - tg;
    }
    __syncthreads();

    // ---- stage 7: MLP head
    if (tid < 128) {
        float acc = __ldg(fb1 + tid);
        #pragma unroll 8
        for (int k = 0; k < 192; k++)
            acc = fmaf(comb_s[k], __ldg(fW1 + k * 128 + tid), acc);
        z1_s[tid] = fmaxf(acc, 0.f);
    }
    __syncthreads();
    if (tid < 64) {
        float acc = __ldg(fb2 + tid);
        #pragma unroll 8
        for (int k = 0; k < 128; k++)
            acc = fmaf(z1_s[k], __ldg(fW2 + k * 64 + tid), acc);
        z2_s[tid] = fmaxf(acc, 0.f);
    }
    __syncthreads();
    if (tid < 32) {
        float acc = fmaf(z2_s[tid], __ldg(fW3 + tid),
                         z2_s[tid + 32] * __ldg(fW3 + tid + 32));
        #pragma unroll
        for (int o = 16; o; o >>= 1) acc += __shfl_xor_sync(0xffffffffu, acc, o);
        if (tid == 0) {
            float zz = acc + __ldg(fb3);
            out[b] = 1.f / (1.f + __expf(-zz));
        }
    }
}

extern "C" void kernel_launch(void* const* d_in, const int* in_sizes, int n_in,
                              void* d_out, int out_size)
{
    const int*   item_ids = (const int*)  d_in[0];
    const int*   history  = (const int*)  d_in[1];
    const int*   hist_len = (const int*)  d_in[2];
    const float* emb      = (const float*)d_in[3];
    const float* aW1      = (const float*)d_in[4];
    const float* ab1      = (const float*)d_in[5];
    const float* aW2      = (const float*)d_in[6];
    // d_in[7] = ab2 — dropped (softmax shift-invariant)
    const float* fW1      = (const float*)d_in[8];
    const float* fb1      = (const float*)d_in[9];
    const float* fW2      = (const float*)d_in[10];
    const float* fb2      = (const float*)d_in[11];
    const float* fW3      = (const float*)d_in[12];
    const float* fb3      = (const float*)d_in[13];
    float* out = (float*)d_out;

    const int nb = in_sizes[0];  // batch size

    cudaFuncSetAttribute(din_kernel, cudaFuncAttributeMaxDynamicSharedMemorySize, SMEM_BYTES);
    din_kernel<<<nb, NTHREADS, SMEM_BYTES>>>(
        item_ids, history, hist_len, emb,
        aW1, ab1, aW2, fW1, fb1, fW2, fb2, fW3, fb3, out);
}

// round 2
// speedup vs baseline: 1.7993x; 1.7993x over previous
#include <cuda_runtime.h>
#include <math.h>

#define NTHREADS 256
#define HLEN     200
#define DIM      64

// smem layout in floats
#define OFF_HISTT 0        // [64][200] transposed history (d-major)
#define OFF_M     12800    // [64][64]  fused per-batch matrix
#define OFF_TGT   16896    // [64]
#define OFF_C     16960    // [64]      fused bias c_j
#define OFF_SC    17024    // [200]     scores -> softmax weights
#define OFF_RED   17224    // [256]
#define OFF_COMB  17480    // [192]
#define OFF_Z1    17672    // [128]
#define OFF_Z2    17800    // [64]
#define OFF_SPAD  17864    // [1]
#define SMEM_FLOATS 17868
#define SMEM_BYTES  (SMEM_FLOATS * 4)

__global__ __launch_bounds__(NTHREADS, 3)
void din_kernel(const int*   __restrict__ item_ids,
                const int*   __restrict__ history,
                const int*   __restrict__ hist_len,
                const float* __restrict__ emb,
                const float* __restrict__ aW1,
                const float* __restrict__ ab1,
                const float* __restrict__ aW2,
                const float* __restrict__ fW1,
                const float* __restrict__ fb1,
                const float* __restrict__ fW2,
                const float* __restrict__ fb2,
                const float* __restrict__ fW3,
                const float* __restrict__ fb3,
                float*       __restrict__ out)
{
    extern __shared__ float sm[];
    float* histT  = sm + OFF_HISTT;
    float* M_s    = sm + OFF_M;
    float* tgt_s  = sm + OFF_TGT;
    float* c_s    = sm + OFF_C;
    float* sc_s   = sm + OFF_SC;
    float* red_s  = sm + OFF_RED;
    float* comb_s = sm + OFF_COMB;
    float* z1_s   = sm + OFF_Z1;
    float* z2_s   = sm + OFF_Z2;
    float* spad_s = sm + OFF_SPAD;

    const int b    = blockIdx.x;
    const int tid  = threadIdx.x;
    const int lane = tid & 31;
    const int wid  = tid >> 5;

    // ---- S0: target embedding
    if (tid < 16) {
        int iid = item_ids[b];
        ((float4*)tgt_s)[tid] = ((const float4*)(emb + (size_t)iid * DIM))[tid];
    }
    __syncthreads();                                    // sync A

    const int hlen = hist_len[b];

    // ---- S1a: gather history -> transposed smem (zero rows past hlen)
    if (tid < HLEN) {
        const bool live = (tid < hlen);
        const float4* row = live
            ? (const float4*)(emb + (size_t)history[b * HLEN + tid] * DIM)
            : (const float4*)emb;
        #pragma unroll
        for (int c = 0; c < 16; c++) {
            float4 v = make_float4(0.f, 0.f, 0.f, 0.f);
            if (live) v = row[c];
            histT[(4*c+0) * HLEN + tid] = v.x;
            histT[(4*c+1) * HLEN + tid] = v.y;
            histT[(4*c+2) * HLEN + tid] = v.z;
            histT[(4*c+3) * HLEN + tid] = v.w;
        }
    }

    // ---- S1b: fused matrix M[d][j] = A1[d][j] + tgt[d]*A3[d][j]
    {
        const float4* A1 = (const float4*)aW1;                 // rows [0,64)
        const float4* A3 = (const float4*)(aW1 + 128 * DIM);   // rows [128,192)
        #pragma unroll
        for (int it = 0; it < 4; it++) {
            int cc = tid + it * NTHREADS;       // float4 chunk 0..1023
            int d  = cc >> 4;
            float t = tgt_s[d];
            float4 a1 = A1[cc], a3 = A3[cc], m;
            m.x = fmaf(t, a3.x, a1.x);
            m.y = fmaf(t, a3.y, a1.y);
            m.z = fmaf(t, a3.z, a1.z);
            m.w = fmaf(t, a3.w, a1.w);
            ((float4*)M_s)[cc] = m;
        }
    }

    // ---- S1c: c_j partials: sum_d tgt[d]*A2[d][j] over 16-d slice
    {
        int jj = tid & 63, g = tid >> 6;
        const float* A2 = aW1 + 64 * DIM;
        float p = 0.f;
        #pragma unroll
        for (int d = g * 16; d < g * 16 + 16; d++)
            p = fmaf(tgt_s[d], __ldg(A2 + d * DIM + jj), p);
        red_s[tid] = p;
    }
    __syncthreads();                                    // sync B

    // ---- S2: finalize c_j; stage relu(c)*w2 for s_pad
    if (tid < DIM) {
        float c = __ldg(ab1 + tid) + red_s[tid] + red_s[64 + tid]
                + red_s[128 + tid] + red_s[192 + tid];
        c_s[tid]  = c;
        z1_s[tid] = fmaxf(c, 0.f) * __ldg(aW2 + tid);
    }
    __syncthreads();                                    // sync C

    // ---- S3a: warp 0 reduces s_pad (others proceed straight into GEMM)
    if (wid == 0) {
        float v = z1_s[lane] + z1_s[lane + 32];
        #pragma unroll
        for (int o = 16; o; o >>= 1) v += __shfl_xor_sync(0xffffffffu, v, o);
        if (lane == 0) spad_s[0] = v;
    }

    // ---- S3b: scores GEMM. thread = (tl, tj): 4 rows x 4 cols tile.
    const int tj = tid & 15;
    const int tl = tid >> 4;
    const int j0 = tj << 2;
    const float4 w2v = ((const float4*)aW2)[tj];
    const float4 c4  = ((const float4*)c_s)[tj];

    for (int l_base = 0; l_base < hlen; l_base += 64) {
        int l0 = l_base + (tl << 2);
        if (l0 < HLEN) {       // warp-uniform (tl pairs per warp)
            float acc[4][4];
            #pragma unroll
            for (int i = 0; i < 4; i++)
                #pragma unroll
                for (int k = 0; k < 4; k++) acc[i][k] = 0.f;

            const float* hp = histT + l0;
            const float* mp = M_s + j0;
            #pragma unroll 4
            for (int d = 0; d < DIM; d++) {
                float4 h = *(const float4*)(hp + d * HLEN);
                float4 m = *(const float4*)(mp + (d << 6));
                acc[0][0] = fmaf(h.x, m.x, acc[0][0]);
                acc[0][1] = fmaf(h.x, m.y, acc[0][1]);
                acc[0][2] = fmaf(h.x, m.z, acc[0][2]);
                acc[0][3] = fmaf(h.x, m.w, acc[0][3]);
                acc[1][0] = fmaf(h.y, m.x, acc[1][0]);
                acc[1][1] = fmaf(h.y, m.y, acc[1][1]);
                acc[1][2] = fmaf(h.y, m.z, acc[1][2]);
                acc[1][3] = fmaf(h.y, m.w, acc[1][3]);
                acc[2][0] = fmaf(h.z, m.x, acc[2][0]);
                acc[2][1] = fmaf(h.z, m.y, acc[2][1]);
                acc[2][2] = fmaf(h.z, m.z, acc[2][2]);
                acc[2][3] = fmaf(h.z, m.w, acc[2][3]);
                acc[3][0] = fmaf(h.w, m.x, acc[3][0]);
                acc[3][1] = fmaf(h.w, m.y, acc[3][1]);
                acc[3][2] = fmaf(h.w, m.z, acc[3][2]);
                acc[3][3] = fmaf(h.w, m.w, acc[3][3]);
            }

            float s[4];
            #pragma unroll
            for (int i = 0; i < 4; i++) {
                float t0 = fmaxf(acc[i][0] + c4.x, 0.f) * w2v.x;
                t0 = fmaf(fmaxf(acc[i][1] + c4.y, 0.f), w2v.y, t0);
                t0 = fmaf(fmaxf(acc[i][2] + c4.z, 0.f), w2v.z, t0);
                t0 = fmaf(fmaxf(acc[i][3] + c4.w, 0.f), w2v.w, t0);
                s[i] = t0;
            }
            // reduce over 16 tj lanes (xor < 16 stays inside half-warp)
            #pragma unroll
            for (int o = 1; o < 16; o <<= 1) {
                s[0] += __shfl_xor_sync(0xffffffffu, s[0], o);
                s[1] += __shfl_xor_sync(0xffffffffu, s[1], o);
                s[2] += __shfl_xor_sync(0xffffffffu, s[2], o);
                s[3] += __shfl_xor_sync(0xffffffffu, s[3], o);
            }
            if (tj == 0)
                *(float4*)(sc_s + l0) = make_float4(s[0], s[1], s[2], s[3]);
        }
    }
    __syncthreads();                                    // sync D

    // ---- S4: fill padded-row scores with s_pad
    {
        float sp = spad_s[0];
        int filled = (hlen + 63) & ~63;
        if (filled > HLEN) filled = HLEN;
        for (int l = filled + tid; l < HLEN; l += NTHREADS) sc_s[l] = sp;
    }
    __syncthreads();                                    // sync E

    // ---- S5: softmax over sc_s[0..199]
    {
        float v = (tid < HLEN) ? sc_s[tid] : -INFINITY;
        float m = v;
        #pragma unroll
        for (int o = 16; o; o >>= 1) m = fmaxf(m, __shfl_xor_sync(0xffffffffu, m, o));
        if (lane == 0) red_s[wid] = m;
        __syncthreads();
        float mm = red_s[0];
        #pragma unroll
        for (int w = 1; w < 8; w++) mm = fmaxf(mm, red_s[w]);

        float e = (tid < HLEN) ? __expf(v - mm) : 0.f;
        float ssum = e;
        #pragma unroll
        for (int o = 16; o; o >>= 1) ssum += __shfl_xor_sync(0xffffffffu, ssum, o);
        if (lane == 0) red_s[8 + wid] = ssum;
        __syncthreads();
        float tot = red_s[8];
        #pragma unroll
        for (int w = 1; w < 8; w++) tot += red_s[8 + w];
        float inv = 1.f / tot;
        if (tid < HLEN) sc_s[tid] = e * inv;
    }
    __syncthreads();

    // ---- S6: pooled[d] = sum_l w[l]*histT[d][l] (pads: hist=0 -> contribute 0)
    if (tid < 128) {
        int d = tid & 63, q = tid >> 6;         // two 100-long halves
        const float4* hp = (const float4*)(histT + d * HLEN + q * 100);
        const float4* wp = (const float4*)(sc_s + q * 100);
        float p = 0.f;
        #pragma unroll 5
        for (int i = 0; i < 25; i++) {
            float4 h = hp[i], w = wp[i];
            p = fmaf(h.x, w.x, p);
            p = fmaf(h.y, w.y, p);
            p = fmaf(h.z, w.z, p);
            p = fmaf(h.w, w.w, p);
        }
        red_s[tid] = p;
    }
    __syncthreads();
    if (tid < DIM) {
        float pooled = red_s[tid] + red_s[64 + tid];
        float tg = tgt_s[tid];
        comb_s[tid]        = tg;
        comb_s[64 + tid]   = pooled;
        comb_s[128 + tid]  = pooled - tg;
    }
    __syncthreads();

    // ---- S7: MLP head
    if (tid < 128) {
        float acc = __ldg(fb1 + tid);
        #pragma unroll 8
        for (int k = 0; k < 192; k++)
            acc = fmaf(comb_s[k], __ldg(fW1 + k * 128 + tid), acc);
        z1_s[tid] = fmaxf(acc, 0.f);
    }
    __syncthreads();
    if (tid < 64) {
        float acc = __ldg(fb2 + tid);
        #pragma unroll 8
        for (int k = 0; k < 128; k++)
            acc = fmaf(z1_s[k], __ldg(fW2 + k * 64 + tid), acc);
        z2_s[tid] = fmaxf(acc, 0.f);
    }
    __syncthreads();
    if (tid < 32) {
        float acc = fmaf(z2_s[tid], __ldg(fW3 + tid),
                         z2_s[tid + 32] * __ldg(fW3 + tid + 32));
        #pragma unroll
        for (int o = 16; o; o >>= 1) acc += __shfl_xor_sync(0xffffffffu, acc, o);
        if (tid == 0) {
            float zz = acc + __ldg(fb3);
            out[b] = 1.f / (1.f + __expf(-zz));
        }
    }
}

extern "C" void kernel_launch(void* const* d_in, const int* in_sizes, int n_in,
                              void* d_out, int out_size)
{
    const int*   item_ids = (const int*)  d_in[0];
    const int*   history  = (const int*)  d_in[1];
    const int*   hist_len = (const int*)  d_in[2];
    const float* emb      = (const float*)d_in[3];
    const float* aW1      = (const float*)d_in[4];
    const float* ab1      = (const float*)d_in[5];
    const float* aW2      = (const float*)d_in[6];
    // d_in[7] = ab2 — dropped (softmax shift-invariant)
    const float* fW1      = (const float*)d_in[8];
    const float* fb1      = (const float*)d_in[9];
    const float* fW2      = (const float*)d_in[10];
    const float* fb2      = (const float*)d_in[11];
    const float* fW3      = (const float*)d_in[12];
    const float* fb3      = (const float*)d_in[13];
    float* out = (float*)d_out;

    const int nb = in_sizes[0];

    cudaFuncSetAttribute(din_kernel, cudaFuncAttributeMaxDynamicSharedMemorySize, SMEM_BYTES);
    din_kernel<<<nb, NTHREADS, SMEM_BYTES>>>(
        item_ids, history, hist_len, emb,
        aW1, ab1, aW2, fW1, fb1, fW2, fb2, fW3, fb3, out);
}